// round 14
// baseline (speedup 1.0000x reference)
#include <cuda_runtime.h>
#include <cuda_fp16.h>
#include <stdint.h>

#define BB 8
#define NN 4096
#define NEG_SLOPE 0.01f
#define KSPLIT 2

// GEMM: M=512 ((b,f) rows), N=4096 (i), K=4096 (j), fp16 single pass.
// CTA tile 128x128, K chunk 64, K-split 2. B read from mask[j][i] via LDSM.trans.
#define STAGE_BYTES 32768          // A 16KB + B 16KB
#define NSTAGE 3
#define SMEM_DYN (NSTAGE * STAGE_BYTES)   // 96KB -> 2 CTAs/SM

// -------- scratch (device globals; no allocation allowed) --------
__device__ __half g_mask[(size_t)NN * NN];         // mask[j][i] = adj[j+1][i]>0 (j=4095 -> 0)
__device__ __half g_hT[(size_t)BB * 64 * NN];      // hT[b][f][n], row (b*64+f)
__device__ float g_s1[BB * NN];
__device__ float g_s2p[KSPLIT][BB * NN];           // per-K-slice partials
__device__ float g_hsumP[16][BB][64];              // per-block partials
__device__ __align__(16) float g_hsum[BB * 64];

// -------- helpers --------
__device__ __forceinline__ uint32_t smem_u32(const void* p) {
    uint32_t a;
    asm("{ .reg .u64 t; cvta.to.shared.u64 t, %1; cvt.u32.u64 %0, t; }" : "=r"(a) : "l"(p));
    return a;
}
#define SW128(x) ((x) ^ (((x) >> 3) & 0x70))
__device__ __forceinline__ void cp16(uint32_t s, const void* g) {
    asm volatile("cp.async.cg.shared.global [%0], [%1], 16;" :: "r"(s), "l"(g) : "memory");
}
#define CP_COMMIT() asm volatile("cp.async.commit_group;" ::: "memory")

__device__ __forceinline__ void mma_f16(float* c, const uint32_t* A, const uint32_t* B) {
    asm volatile(
        "mma.sync.aligned.m16n8k16.row.col.f32.f16.f16.f32 "
        "{%0,%1,%2,%3}, {%4,%5,%6,%7}, {%8,%9}, {%0,%1,%2,%3};"
        : "+f"(c[0]), "+f"(c[1]), "+f"(c[2]), "+f"(c[3])
        : "r"(A[0]), "r"(A[1]), "r"(A[2]), "r"(A[3]), "r"(B[0]), "r"(B[1]));
}
#define LDSM4(r0, r1, r2, r3, addr) \
    asm volatile("ldmatrix.sync.aligned.m8n8.x4.shared.b16 {%0,%1,%2,%3}, [%4];" \
                 : "=r"(r0), "=r"(r1), "=r"(r2), "=r"(r3) : "r"(addr))
#define LDSM4T(r0, r1, r2, r3, addr) \
    asm volatile("ldmatrix.sync.aligned.m8n8.x4.trans.shared.b16 {%0,%1,%2,%3}, [%4];" \
                 : "=r"(r0), "=r"(r1), "=r"(r2), "=r"(r3) : "r"(addr))

// -------- kernel: flat streaming convert (16B stores, 8 outstanding loads) --------
// mask rows 0..4094 are a contiguous map of adj rows 1..4095; last row = 0.
__global__ void __launch_bounds__(256) k_convert(const int* __restrict__ adj) {
    const size_t total8 = (size_t)(NN - 1) * NN / 8;   // uint4-out units (8 ints in)
    size_t gid = (size_t)blockIdx.x * 256 + threadIdx.x;
    size_t stride = (size_t)gridDim.x * 256;
    const int4* src = reinterpret_cast<const int4*>(adj + NN);
    uint4* dst = reinterpret_cast<uint4*>(g_mask);
#pragma unroll
    for (int it = 0; it < 4; it++) {
        size_t t = gid + (size_t)it * stride;
        if (t < total8) {
            int4 v0 = src[2 * t];
            int4 v1 = src[2 * t + 1];
            uint4 o;
            o.x = (v0.x > 0 ? 0x3C00u : 0u) | (v0.y > 0 ? 0x3C000000u : 0u);
            o.y = (v0.z > 0 ? 0x3C00u : 0u) | (v0.w > 0 ? 0x3C000000u : 0u);
            o.z = (v1.x > 0 ? 0x3C00u : 0u) | (v1.y > 0 ? 0x3C000000u : 0u);
            o.w = (v1.z > 0 ? 0x3C00u : 0u) | (v1.w > 0 ? 0x3C000000u : 0u);
            dst[t] = o;
        }
    }
    if (gid < 512)   // zero last row: 4096 halves = 512 uint4
        reinterpret_cast<uint4*>(g_mask + (size_t)(NN - 1) * NN)[gid] =
            make_uint4(0u, 0u, 0u, 0u);
}

// -------- kernel 2: h = inp@W^T + b (row 0 zeroed); fp16 h + s1 + hsum partials --------
__global__ void __launch_bounds__(256) k_compute_h(const float* __restrict__ inp,
                                                   const float* __restrict__ W_w,
                                                   const float* __restrict__ W_b,
                                                   const float* __restrict__ a) {
    __shared__ __align__(16) float Wsh[64 * 64];
    __shared__ float bsh[64];
    __shared__ float wred[8][64];
    int tid = threadIdx.x, lane = tid & 31, wid = tid >> 5;
    int b = blockIdx.y, nb = blockIdx.x;
    int n = nb * 256 + tid;
    for (int i = tid; i < 64 * 64; i += 256) Wsh[i] = W_w[i];
    if (tid < 64) bsh[tid] = W_b[tid];
    __syncthreads();

    float x[64];
    const float4* src = reinterpret_cast<const float4*>(inp + ((size_t)b * NN + n) * 64);
#pragma unroll
    for (int q = 0; q < 16; q++) {
        float4 v = src[q];
        x[4 * q] = v.x; x[4 * q + 1] = v.y; x[4 * q + 2] = v.z; x[4 * q + 3] = v.w;
    }
    float s1 = 0.f;
    for (int f = 0; f < 64; f++) {
        const float4* wr = reinterpret_cast<const float4*>(Wsh + f * 64);
        float t0 = bsh[f], t1 = 0.f, t2 = 0.f, t3 = 0.f;
#pragma unroll
        for (int q = 0; q < 16; q += 4) {
            float4 w0 = wr[q], w1 = wr[q + 1], w2 = wr[q + 2], w3 = wr[q + 3];
            t0 = fmaf(x[4*q+0],  w0.x, t0); t0 = fmaf(x[4*q+1],  w0.y, t0);
            t0 = fmaf(x[4*q+2],  w0.z, t0); t0 = fmaf(x[4*q+3],  w0.w, t0);
            t1 = fmaf(x[4*q+4],  w1.x, t1); t1 = fmaf(x[4*q+5],  w1.y, t1);
            t1 = fmaf(x[4*q+6],  w1.z, t1); t1 = fmaf(x[4*q+7],  w1.w, t1);
            t2 = fmaf(x[4*q+8],  w2.x, t2); t2 = fmaf(x[4*q+9],  w2.y, t2);
            t2 = fmaf(x[4*q+10], w2.z, t2); t2 = fmaf(x[4*q+11], w2.w, t2);
            t3 = fmaf(x[4*q+12], w3.x, t3); t3 = fmaf(x[4*q+13], w3.y, t3);
            t3 = fmaf(x[4*q+14], w3.z, t3); t3 = fmaf(x[4*q+15], w3.w, t3);
        }
        float acc = (t0 + t1) + (t2 + t3);
        if (n == 0) acc = 0.f;
        g_hT[((size_t)b * 64 + f) * NN + n] = __float2half(acc);
        s1 = fmaf(acc, a[(size_t)f * NN + n], s1);
        float v = acc;
#pragma unroll
        for (int off = 16; off > 0; off >>= 1)
            v += __shfl_xor_sync(0xFFFFFFFFu, v, off);
        if (lane == 0) wred[wid][f] = v;
    }
    g_s1[b * NN + n] = s1;
    __syncthreads();
    if (tid < 64) {
        float t = 0.f;
#pragma unroll
        for (int w = 0; w < 8; w++) t += wred[w][tid];
        g_hsumP[nb][b][tid] = t;
    }
}

// -------- kernel 3: finish hsum (idempotent; duplicated for profiler slotting) --------
__global__ void k_hsum_final() {
    int b = threadIdx.x >> 6, f = threadIdx.x & 63;   // 512 threads
    float t = 0.f;
#pragma unroll
    for (int p = 0; p < 16; p++) t += g_hsumP[p][b][f];
    g_hsum[b * 64 + f] = t;
}

// -------- kernel 4: big GEMM (fp16 mma, A LDSM + B LDSM.trans, 3-stage 1-sync) --------
__device__ __forceinline__ void load_chunk(uint32_t stage, const char* Ah,
                                           const char* Bm, int c, int tid) {
    // A: 128 (b,f)-rows x 128B (64 j), SW128
    size_t koffA = (size_t)c * 128;
#pragma unroll
    for (int p = 0; p < 4; p++) {
        int q = tid + p * 256;
        int row = q >> 3, cb = (q & 7) * 16;
        cp16(stage + SW128((uint32_t)(row * 128 + cb)),
             Ah + (size_t)row * 8192 + koffA + cb);
    }
    // B: 64 j-rows x 256B (128 i), row-swizzle ^((row&15)<<4)
    size_t koffB = (size_t)c * 64 * 8192;
#pragma unroll
    for (int p = 0; p < 4; p++) {
        int q = tid + p * 256;
        int row = q >> 4, cb = (q & 15) * 16;
        uint32_t din = (uint32_t)cb ^ (uint32_t)((row & 15) << 4);
        cp16(stage + 16384u + (uint32_t)(row * 256) + din,
             Bm + koffB + (size_t)row * 8192 + cb);
    }
}

__global__ void __launch_bounds__(256, 2) k_gemm(const float* __restrict__ a) {
    extern __shared__ char smem[];
    uint32_t sb = smem_u32(smem);
    int tid = threadIdx.x, lane = tid & 31, wid = tid >> 5;
    int wm = wid & 3, wn = wid >> 2;          // warp tile: rows wm*32, cols wn*64
    int mtile = blockIdx.x, i0 = blockIdx.y * 128;
    int kslice = blockIdx.z, c0 = kslice * 32;  // 32 chunks of 64 per slice

    const char* Ah = (const char*)g_hT + (size_t)mtile * 128 * 8192;
    const char* Bm = (const char*)g_mask + (size_t)i0 * 2;

    float acc[2][8][4];
#pragma unroll
    for (int mt = 0; mt < 2; mt++)
#pragma unroll
        for (int nt = 0; nt < 8; nt++)
#pragma unroll
            for (int r = 0; r < 4; r++) acc[mt][nt][r] = 0.f;

    // A LDSM addressing (SW128)
    uint32_t cx = (uint32_t)((lane & 7) << 4);
    uint32_t aoff = (uint32_t)(wm * 32 + (lane & 15)) * 128u;
    uint32_t khA = (uint32_t)(((lane >> 4) & 1) << 4);
    // B LDSM.trans addressing: addr = row*256 + (col ^ ((row&15)<<4))
    uint32_t bj = (uint32_t)(lane & 15);
    uint32_t bcx = bj << 4;
    uint32_t bbase = bj * 256u + (uint32_t)(wn * 64 + ((lane >> 4) << 3)) * 2u;

    // prologue: chunks 0,1
    load_chunk(sb, Ah, Bm, c0, tid);
    CP_COMMIT();
    load_chunk(sb + STAGE_BYTES, Ah, Bm, c0 + 1, tid);
    CP_COMMIT();

    for (int c = 0; c < 32; c++) {
        asm volatile("cp.async.wait_group 1;" ::: "memory");
        __syncthreads();   // chunk c ready; all warps done computing c-1
        if (c + 2 < 32)
            load_chunk(sb + (uint32_t)((c + 2) % NSTAGE) * STAGE_BYTES, Ah, Bm, c0 + c + 2, tid);
        CP_COMMIT();
        uint32_t so = sb + (uint32_t)(c % NSTAGE) * STAGE_BYTES;
#pragma unroll
        for (int ks = 0; ks < 4; ks++) {
            uint32_t kA = ((uint32_t)(ks * 32) + khA) ^ cx;
            uint32_t bfr[8][2];
#pragma unroll
            for (int ntp = 0; ntp < 4; ntp++) {
                uint32_t boffs = (bbase + (uint32_t)(ntp * 32)) ^ bcx;
                LDSM4T(bfr[2 * ntp][0], bfr[2 * ntp][1], bfr[2 * ntp + 1][0], bfr[2 * ntp + 1][1],
                       so + 16384u + (uint32_t)(ks * 4096) + boffs);
            }
            uint32_t ah[2][4];
#pragma unroll
            for (int mt = 0; mt < 2; mt++)
                LDSM4(ah[mt][0], ah[mt][1], ah[mt][2], ah[mt][3],
                      so + aoff + (uint32_t)mt * 2048 + kA);
#pragma unroll
            for (int mt = 0; mt < 2; mt++)
#pragma unroll
                for (int nt = 0; nt < 8; nt++)
                    mma_f16(acc[mt][nt], ah[mt], bfr[nt]);
        }
    }

    // epilogue: s2p[kslice][b][i] = sum_f C[(b,f)][i] * a2[f][i]
    __syncthreads();
    int tig = lane & 3, grp = lane >> 2;
    float* a2s = (float*)smem;                        // [64][129]
    float* part = (float*)(smem + 64 * 129 * 4);      // [8 warps][64]
    for (int idx = tid; idx < 64 * 128; idx += 256) {
        int f = idx >> 7, cc = idx & 127;
        a2s[f * 129 + cc] = a[(size_t)(64 + f) * NN + i0 + cc];
    }
    __syncthreads();

    float p[8][2];
#pragma unroll
    for (int nt = 0; nt < 8; nt++) { p[nt][0] = 0.f; p[nt][1] = 0.f; }
#pragma unroll
    for (int mt = 0; mt < 2; mt++) {
        int f0 = (wm * 32 + mt * 16 + grp) & 63;
        int f1 = (wm * 32 + mt * 16 + grp + 8) & 63;
#pragma unroll
        for (int nt = 0; nt < 8; nt++) {
            int col = wn * 64 + nt * 8 + tig * 2;
            p[nt][0] += acc[mt][nt][0] * a2s[f0 * 129 + col] +
                        acc[mt][nt][2] * a2s[f1 * 129 + col];
            p[nt][1] += acc[mt][nt][1] * a2s[f0 * 129 + col + 1] +
                        acc[mt][nt][3] * a2s[f1 * 129 + col + 1];
        }
    }
#pragma unroll
    for (int off = 16; off >= 4; off >>= 1)
#pragma unroll
        for (int nt = 0; nt < 8; nt++) {
            p[nt][0] += __shfl_xor_sync(0xFFFFFFFFu, p[nt][0], off);
            p[nt][1] += __shfl_xor_sync(0xFFFFFFFFu, p[nt][1], off);
        }
    if (lane < 4) {
#pragma unroll
        for (int nt = 0; nt < 8; nt++) {
            part[wid * 64 + nt * 8 + tig * 2]     = p[nt][0];
            part[wid * 64 + nt * 8 + tig * 2 + 1] = p[nt][1];
        }
    }
    __syncthreads();
    {
        int bloc = tid >> 7, col = tid & 127;
        int wnn = col >> 6, c64 = col & 63;
        int w0 = wnn * 4 + bloc * 2;   // warps covering this (batch, col-block)
        float v = part[w0 * 64 + c64] + part[(w0 + 1) * 64 + c64];
        g_s2p[kslice][(size_t)(mtile * 2 + bloc) * NN + i0 + col] = v;
    }
}

// -------- kernel 5: out[b,n,f] = leaky(s[b,n] * hsum[b,f]), 2 float4 per thread --------
__global__ void __launch_bounds__(256) k_out(float* __restrict__ out) {
    int b = blockIdx.y, tid = threadIdx.x;
    int n = blockIdx.x * 32 + (tid >> 3);
    int qp = (tid & 7) * 2;
    int off = b * NN + n;
    float s = 0.f;
    if (n != 0) {
        s = g_s1[off] + g_s2p[0][off] + g_s2p[1][off];
    }
    const float4* hsp = reinterpret_cast<const float4*>(g_hsum + b * 64);
    float4 ha = hsp[qp], hb = hsp[qp + 1];
    float4 va, vb;
    va.x = s * ha.x; va.y = s * ha.y; va.z = s * ha.z; va.w = s * ha.w;
    vb.x = s * hb.x; vb.y = s * hb.y; vb.z = s * hb.z; vb.w = s * hb.w;
    va.x = va.x >= 0.f ? va.x : NEG_SLOPE * va.x;
    va.y = va.y >= 0.f ? va.y : NEG_SLOPE * va.y;
    va.z = va.z >= 0.f ? va.z : NEG_SLOPE * va.z;
    va.w = va.w >= 0.f ? va.w : NEG_SLOPE * va.w;
    vb.x = vb.x >= 0.f ? vb.x : NEG_SLOPE * vb.x;
    vb.y = vb.y >= 0.f ? vb.y : NEG_SLOPE * vb.y;
    vb.z = vb.z >= 0.f ? vb.z : NEG_SLOPE * vb.z;
    vb.w = vb.w >= 0.f ? vb.w : NEG_SLOPE * vb.w;
    float4* dst = reinterpret_cast<float4*>(out + ((size_t)b * NN + n) * 64);
    dst[qp] = va;
    dst[qp + 1] = vb;
}

extern "C" void kernel_launch(void* const* d_in, const int* in_sizes, int n_in,
                              void* d_out, int out_size) {
    const float* inp = (const float*)d_in[0];
    const int*   adj = (const int*)d_in[1];
    const float* W_w = (const float*)d_in[2];
    const float* W_b = (const float*)d_in[3];
    const float* a   = (const float*)d_in[4];
    float* out = (float*)d_out;
    cudaFuncSetAttribute(k_gemm, cudaFuncAttributeMaxDynamicSharedMemorySize, SMEM_DYN);
    k_compute_h<<<dim3(16, 8), 256>>>(inp, W_w, W_b, a);        // launch 1
    k_hsum_final<<<1, 512>>>();                                 // launch 2
    k_hsum_final<<<1, 512>>>();                                 // launch 3 (idempotent dup)
    k_convert<<<2048, 256>>>(adj);                              // launch 4  <- ncu slot
    k_gemm<<<dim3(4, 32, KSPLIT), 256, SMEM_DYN>>>(a);          // launch 5
    k_out<<<dim3(128, 8), 256>>>(out);                          // launch 6
}

// round 15
// speedup vs baseline: 1.1668x; 1.1668x over previous
#include <cuda_runtime.h>
#include <cuda_fp16.h>
#include <stdint.h>

#define BB 8
#define NN 4096
#define NEG_SLOPE 0.01f
#define KSPLIT 2

// GEMM: M=512 ((b,f) rows), N=4096 (i), K=4096 (j), fp16 single pass.
// CTA tile 128x128, K chunk 64, K-split 2. B read from mask[j][i] via LDSM.trans.
#define STAGE_BYTES 32768          // A 16KB + B 16KB
#define NSTAGE 3
#define SMEM_DYN (NSTAGE * STAGE_BYTES)   // 96KB -> 2 CTAs/SM

// -------- scratch (device globals; no allocation allowed) --------
__device__ __half g_mask[(size_t)NN * NN];         // mask[j][i] = adj[j+1][i]>0 (j=4095 -> 0)
__device__ __half g_hT[(size_t)BB * 64 * NN];      // hT[b][f][n], row (b*64+f)
__device__ float g_s1[BB * NN];
__device__ float g_s2p[KSPLIT][BB * NN];           // per-K-slice partials
__device__ __align__(16) float g_hsum[BB * 64];

// -------- helpers --------
__device__ __forceinline__ uint32_t smem_u32(const void* p) {
    uint32_t a;
    asm("{ .reg .u64 t; cvta.to.shared.u64 t, %1; cvt.u32.u64 %0, t; }" : "=r"(a) : "l"(p));
    return a;
}
#define SW128(x) ((x) ^ (((x) >> 3) & 0x70))
__device__ __forceinline__ void cp16(uint32_t s, const void* g) {
    asm volatile("cp.async.cg.shared.global [%0], [%1], 16;" :: "r"(s), "l"(g) : "memory");
}
#define CP_COMMIT() asm volatile("cp.async.commit_group;" ::: "memory")

__device__ __forceinline__ void mma_f16(float* c, const uint32_t* A, const uint32_t* B) {
    asm volatile(
        "mma.sync.aligned.m16n8k16.row.col.f32.f16.f16.f32 "
        "{%0,%1,%2,%3}, {%4,%5,%6,%7}, {%8,%9}, {%0,%1,%2,%3};"
        : "+f"(c[0]), "+f"(c[1]), "+f"(c[2]), "+f"(c[3])
        : "r"(A[0]), "r"(A[1]), "r"(A[2]), "r"(A[3]), "r"(B[0]), "r"(B[1]));
}
#define LDSM4(r0, r1, r2, r3, addr) \
    asm volatile("ldmatrix.sync.aligned.m8n8.x4.shared.b16 {%0,%1,%2,%3}, [%4];" \
                 : "=r"(r0), "=r"(r1), "=r"(r2), "=r"(r3) : "r"(addr))
#define LDSM4T(r0, r1, r2, r3, addr) \
    asm volatile("ldmatrix.sync.aligned.m8n8.x4.trans.shared.b16 {%0,%1,%2,%3}, [%4];" \
                 : "=r"(r0), "=r"(r1), "=r"(r2), "=r"(r3) : "r"(addr))

// -------- kernel 1: flat streaming convert (16B stores) --------
__global__ void __launch_bounds__(256) k_convert(const int* __restrict__ adj) {
    const size_t total8 = (size_t)(NN - 1) * NN / 8;   // uint4-out units (8 ints in)
    size_t gid = (size_t)blockIdx.x * 256 + threadIdx.x;
    size_t stride = (size_t)gridDim.x * 256;
    const int4* src = reinterpret_cast<const int4*>(adj + NN);
    uint4* dst = reinterpret_cast<uint4*>(g_mask);
#pragma unroll
    for (int it = 0; it < 4; it++) {
        size_t t = gid + (size_t)it * stride;
        if (t < total8) {
            int4 v0 = src[2 * t];
            int4 v1 = src[2 * t + 1];
            uint4 o;
            o.x = (v0.x > 0 ? 0x3C00u : 0u) | (v0.y > 0 ? 0x3C000000u : 0u);
            o.y = (v0.z > 0 ? 0x3C00u : 0u) | (v0.w > 0 ? 0x3C000000u : 0u);
            o.z = (v1.x > 0 ? 0x3C00u : 0u) | (v1.y > 0 ? 0x3C000000u : 0u);
            o.w = (v1.z > 0 ? 0x3C00u : 0u) | (v1.w > 0 ? 0x3C000000u : 0u);
            dst[t] = o;
        }
    }
    if (gid < 512)
        reinterpret_cast<uint4*>(g_mask + (size_t)(NN - 1) * NN)[gid] =
            make_uint4(0u, 0u, 0u, 0u);
}

// -------- kernel 2: h = inp@W^T + b (row 0 zeroed); fp16 h + s1 (no hsum) --------
__global__ void __launch_bounds__(128) k_compute_h(const float* __restrict__ inp,
                                                   const float* __restrict__ W_w,
                                                   const float* __restrict__ W_b,
                                                   const float* __restrict__ a) {
    __shared__ __align__(16) float Wsh[64 * 64];
    __shared__ float bsh[64];
    int tid = threadIdx.x;
    int b = blockIdx.y, nb = blockIdx.x;
    int n = nb * 128 + tid;
    for (int i = tid; i < 64 * 64; i += 128) Wsh[i] = W_w[i];
    if (tid < 64) bsh[tid] = W_b[tid];
    __syncthreads();

    float x[64];
    const float4* src = reinterpret_cast<const float4*>(inp + ((size_t)b * NN + n) * 64);
#pragma unroll
    for (int q = 0; q < 16; q++) {
        float4 v = src[q];
        x[4 * q] = v.x; x[4 * q + 1] = v.y; x[4 * q + 2] = v.z; x[4 * q + 3] = v.w;
    }
    float s1 = 0.f;
#pragma unroll 4
    for (int f = 0; f < 64; f++) {
        const float4* wr = reinterpret_cast<const float4*>(Wsh + f * 64);
        float t0 = bsh[f], t1 = 0.f, t2 = 0.f, t3 = 0.f;
#pragma unroll
        for (int q = 0; q < 16; q += 4) {
            float4 w0 = wr[q], w1 = wr[q + 1], w2 = wr[q + 2], w3 = wr[q + 3];
            t0 = fmaf(x[4*q+0],  w0.x, t0); t0 = fmaf(x[4*q+1],  w0.y, t0);
            t0 = fmaf(x[4*q+2],  w0.z, t0); t0 = fmaf(x[4*q+3],  w0.w, t0);
            t1 = fmaf(x[4*q+4],  w1.x, t1); t1 = fmaf(x[4*q+5],  w1.y, t1);
            t1 = fmaf(x[4*q+6],  w1.z, t1); t1 = fmaf(x[4*q+7],  w1.w, t1);
            t2 = fmaf(x[4*q+8],  w2.x, t2); t2 = fmaf(x[4*q+9],  w2.y, t2);
            t2 = fmaf(x[4*q+10], w2.z, t2); t2 = fmaf(x[4*q+11], w2.w, t2);
            t3 = fmaf(x[4*q+12], w3.x, t3); t3 = fmaf(x[4*q+13], w3.y, t3);
            t3 = fmaf(x[4*q+14], w3.z, t3); t3 = fmaf(x[4*q+15], w3.w, t3);
        }
        float acc = (t0 + t1) + (t2 + t3);
        if (n == 0) acc = 0.f;
        g_hT[((size_t)b * 64 + f) * NN + n] = __float2half(acc);
        s1 = fmaf(acc, a[(size_t)f * NN + n], s1);
    }
    g_s1[b * NN + n] = s1;
}

// -------- kernel 3: hsum[b][f] = sum_n h (from fp16 hT rows) --------
__global__ void __launch_bounds__(256) k_hsum(/* grid (64,8) */) {
    __shared__ float red[256];
    int b = blockIdx.y, f = blockIdx.x, tid = threadIdx.x;
    const __half2* row = reinterpret_cast<const __half2*>(g_hT + ((size_t)b * 64 + f) * NN);
    float s = 0.f;
#pragma unroll
    for (int p = 0; p < 8; p++) {
        float2 v = __half22float2(row[tid + p * 256]);
        s += v.x + v.y;
    }
    red[tid] = s;
    __syncthreads();
    for (int st = 128; st > 0; st >>= 1) {
        if (tid < st) red[tid] += red[tid + st];
        __syncthreads();
    }
    if (tid == 0) g_hsum[b * 64 + f] = red[0];
}

// -------- kernel 4: big GEMM (fp16 mma, A LDSM + B LDSM.trans, 3-stage 1-sync) --------
__device__ __forceinline__ void load_chunk(uint32_t stage, const char* Ah,
                                           const char* Bm, int c, int tid) {
    size_t koffA = (size_t)c * 128;
#pragma unroll
    for (int p = 0; p < 4; p++) {
        int q = tid + p * 256;
        int row = q >> 3, cb = (q & 7) * 16;
        cp16(stage + SW128((uint32_t)(row * 128 + cb)),
             Ah + (size_t)row * 8192 + koffA + cb);
    }
    size_t koffB = (size_t)c * 64 * 8192;
#pragma unroll
    for (int p = 0; p < 4; p++) {
        int q = tid + p * 256;
        int row = q >> 4, cb = (q & 15) * 16;
        uint32_t din = (uint32_t)cb ^ (uint32_t)((row & 15) << 4);
        cp16(stage + 16384u + (uint32_t)(row * 256) + din,
             Bm + koffB + (size_t)row * 8192 + cb);
    }
}

__global__ void __launch_bounds__(256, 2) k_gemm(const float* __restrict__ a) {
    extern __shared__ char smem[];
    uint32_t sb = smem_u32(smem);
    int tid = threadIdx.x, lane = tid & 31, wid = tid >> 5;
    int wm = wid & 3, wn = wid >> 2;
    int mtile = blockIdx.x, i0 = blockIdx.y * 128;
    int kslice = blockIdx.z, c0 = kslice * 32;

    const char* Ah = (const char*)g_hT + (size_t)mtile * 128 * 8192;
    const char* Bm = (const char*)g_mask + (size_t)i0 * 2;

    float acc[2][8][4];
#pragma unroll
    for (int mt = 0; mt < 2; mt++)
#pragma unroll
        for (int nt = 0; nt < 8; nt++)
#pragma unroll
            for (int r = 0; r < 4; r++) acc[mt][nt][r] = 0.f;

    uint32_t cx = (uint32_t)((lane & 7) << 4);
    uint32_t aoff = (uint32_t)(wm * 32 + (lane & 15)) * 128u;
    uint32_t khA = (uint32_t)(((lane >> 4) & 1) << 4);
    uint32_t bj = (uint32_t)(lane & 15);
    uint32_t bcx = bj << 4;
    uint32_t bbase = bj * 256u + (uint32_t)(wn * 64 + ((lane >> 4) << 3)) * 2u;

    load_chunk(sb, Ah, Bm, c0, tid);
    CP_COMMIT();
    load_chunk(sb + STAGE_BYTES, Ah, Bm, c0 + 1, tid);
    CP_COMMIT();

    for (int c = 0; c < 32; c++) {
        asm volatile("cp.async.wait_group 1;" ::: "memory");
        __syncthreads();
        if (c + 2 < 32)
            load_chunk(sb + (uint32_t)((c + 2) % NSTAGE) * STAGE_BYTES, Ah, Bm, c0 + c + 2, tid);
        CP_COMMIT();
        uint32_t so = sb + (uint32_t)(c % NSTAGE) * STAGE_BYTES;
#pragma unroll
        for (int ks = 0; ks < 4; ks++) {
            uint32_t kA = ((uint32_t)(ks * 32) + khA) ^ cx;
            uint32_t bfr[8][2];
#pragma unroll
            for (int ntp = 0; ntp < 4; ntp++) {
                uint32_t boffs = (bbase + (uint32_t)(ntp * 32)) ^ bcx;
                LDSM4T(bfr[2 * ntp][0], bfr[2 * ntp][1], bfr[2 * ntp + 1][0], bfr[2 * ntp + 1][1],
                       so + 16384u + (uint32_t)(ks * 4096) + boffs);
            }
            uint32_t ah[2][4];
#pragma unroll
            for (int mt = 0; mt < 2; mt++)
                LDSM4(ah[mt][0], ah[mt][1], ah[mt][2], ah[mt][3],
                      so + aoff + (uint32_t)mt * 2048 + kA);
#pragma unroll
            for (int mt = 0; mt < 2; mt++)
#pragma unroll
                for (int nt = 0; nt < 8; nt++)
                    mma_f16(acc[mt][nt], ah[mt], bfr[nt]);
        }
    }

    // epilogue: s2p[kslice][b][i] = sum_f C[(b,f)][i] * a2[f][i]
    __syncthreads();
    int tig = lane & 3, grp = lane >> 2;
    float* a2s = (float*)smem;                        // [64][129]
    float* part = (float*)(smem + 64 * 129 * 4);      // [8 warps][64]
    for (int idx = tid; idx < 64 * 128; idx += 256) {
        int f = idx >> 7, cc = idx & 127;
        a2s[f * 129 + cc] = a[(size_t)(64 + f) * NN + i0 + cc];
    }
    __syncthreads();

    float p[8][2];
#pragma unroll
    for (int nt = 0; nt < 8; nt++) { p[nt][0] = 0.f; p[nt][1] = 0.f; }
#pragma unroll
    for (int mt = 0; mt < 2; mt++) {
        int f0 = (wm * 32 + mt * 16 + grp) & 63;
        int f1 = (wm * 32 + mt * 16 + grp + 8) & 63;
#pragma unroll
        for (int nt = 0; nt < 8; nt++) {
            int col = wn * 64 + nt * 8 + tig * 2;
            p[nt][0] += acc[mt][nt][0] * a2s[f0 * 129 + col] +
                        acc[mt][nt][2] * a2s[f1 * 129 + col];
            p[nt][1] += acc[mt][nt][1] * a2s[f0 * 129 + col + 1] +
                        acc[mt][nt][3] * a2s[f1 * 129 + col + 1];
        }
    }
#pragma unroll
    for (int off = 16; off >= 4; off >>= 1)
#pragma unroll
        for (int nt = 0; nt < 8; nt++) {
            p[nt][0] += __shfl_xor_sync(0xFFFFFFFFu, p[nt][0], off);
            p[nt][1] += __shfl_xor_sync(0xFFFFFFFFu, p[nt][1], off);
        }
    if (lane < 4) {
#pragma unroll
        for (int nt = 0; nt < 8; nt++) {
            part[wid * 64 + nt * 8 + tig * 2]     = p[nt][0];
            part[wid * 64 + nt * 8 + tig * 2 + 1] = p[nt][1];
        }
    }
    __syncthreads();
    {
        int bloc = tid >> 7, col = tid & 127;
        int wnn = col >> 6, c64 = col & 63;
        int w0 = wnn * 4 + bloc * 2;
        float v = part[w0 * 64 + c64] + part[(w0 + 1) * 64 + c64];
        g_s2p[kslice][(size_t)(mtile * 2 + bloc) * NN + i0 + col] = v;
    }
}

// -------- kernel 5: out[b,n,f] = leaky(s[b,n] * hsum[b,f]), 2 float4 per thread --------
__global__ void __launch_bounds__(256) k_out(float* __restrict__ out) {
    int b = blockIdx.y, tid = threadIdx.x;
    int n = blockIdx.x * 32 + (tid >> 3);
    int qp = (tid & 7) * 2;
    int off = b * NN + n;
    float s = 0.f;
    if (n != 0) {
        s = g_s1[off] + g_s2p[0][off] + g_s2p[1][off];
    }
    const float4* hsp = reinterpret_cast<const float4*>(g_hsum + b * 64);
    float4 ha = hsp[qp], hb = hsp[qp + 1];
    float4 va, vb;
    va.x = s * ha.x; va.y = s * ha.y; va.z = s * ha.z; va.w = s * ha.w;
    vb.x = s * hb.x; vb.y = s * hb.y; vb.z = s * hb.z; vb.w = s * hb.w;
    va.x = va.x >= 0.f ? va.x : NEG_SLOPE * va.x;
    va.y = va.y >= 0.f ? va.y : NEG_SLOPE * va.y;
    va.z = va.z >= 0.f ? va.z : NEG_SLOPE * va.z;
    va.w = va.w >= 0.f ? va.w : NEG_SLOPE * va.w;
    vb.x = vb.x >= 0.f ? vb.x : NEG_SLOPE * vb.x;
    vb.y = vb.y >= 0.f ? vb.y : NEG_SLOPE * vb.y;
    vb.z = vb.z >= 0.f ? vb.z : NEG_SLOPE * vb.z;
    vb.w = vb.w >= 0.f ? vb.w : NEG_SLOPE * vb.w;
    float4* dst = reinterpret_cast<float4*>(out + ((size_t)b * NN + n) * 64);
    dst[qp] = va;
    dst[qp + 1] = vb;
}

extern "C" void kernel_launch(void* const* d_in, const int* in_sizes, int n_in,
                              void* d_out, int out_size) {
    const float* inp = (const float*)d_in[0];
    const int*   adj = (const int*)d_in[1];
    const float* W_w = (const float*)d_in[2];
    const float* W_b = (const float*)d_in[3];
    const float* a   = (const float*)d_in[4];
    float* out = (float*)d_out;
    cudaFuncSetAttribute(k_gemm, cudaFuncAttributeMaxDynamicSharedMemorySize, SMEM_DYN);
    k_convert<<<2048, 256>>>(adj);                              // launch 1
    k_compute_h<<<dim3(32, 8), 128>>>(inp, W_w, W_b, a);        // launch 2
    k_hsum<<<dim3(64, 8), 256>>>();                             // launch 3
    k_gemm<<<dim3(4, 32, KSPLIT), 256, SMEM_DYN>>>(a);          // launch 4  <- ncu slot
    k_out<<<dim3(128, 8), 256>>>(out);                          // launch 5
}

// round 16
// speedup vs baseline: 1.1797x; 1.0111x over previous
#include <cuda_runtime.h>
#include <cuda_fp16.h>
#include <stdint.h>

#define BB 8
#define NN 4096
#define NEG_SLOPE 0.01f
#define KSPLIT 2

// GEMM: M=512 ((b,f) rows), N=4096 (i), K=4096 (j), fp16 single pass.
// CTA tile 128x128, K chunk 64, K-split 2. B read from mask[j][i] via LDSM.trans.
#define STAGE_BYTES 32768          // A 16KB + B 16KB
#define NSTAGE 3
#define SMEM_DYN (NSTAGE * STAGE_BYTES)   // 96KB -> 2 CTAs/SM

// -------- scratch (device globals; no allocation allowed) --------
__device__ __half g_mask[(size_t)NN * NN];         // mask[j][i] = adj[j+1][i]>0 (j=4095 -> 0)
__device__ __half g_hT[(size_t)BB * 64 * NN];      // hT[b][f][n], row (b*64+f)
__device__ float g_s1p[2][BB * NN];                // per-f-half partials of s1
__device__ float g_s2p[KSPLIT][BB * NN];           // per-K-slice partials
__device__ __align__(16) float g_hsum[BB * 64];

// -------- helpers --------
__device__ __forceinline__ uint32_t smem_u32(const void* p) {
    uint32_t a;
    asm("{ .reg .u64 t; cvta.to.shared.u64 t, %1; cvt.u32.u64 %0, t; }" : "=r"(a) : "l"(p));
    return a;
}
#define SW128(x) ((x) ^ (((x) >> 3) & 0x70))
__device__ __forceinline__ void cp16(uint32_t s, const void* g) {
    asm volatile("cp.async.cg.shared.global [%0], [%1], 16;" :: "r"(s), "l"(g) : "memory");
}
#define CP_COMMIT() asm volatile("cp.async.commit_group;" ::: "memory")

__device__ __forceinline__ void mma_f16(float* c, const uint32_t* A, const uint32_t* B) {
    asm volatile(
        "mma.sync.aligned.m16n8k16.row.col.f32.f16.f16.f32 "
        "{%0,%1,%2,%3}, {%4,%5,%6,%7}, {%8,%9}, {%0,%1,%2,%3};"
        : "+f"(c[0]), "+f"(c[1]), "+f"(c[2]), "+f"(c[3])
        : "r"(A[0]), "r"(A[1]), "r"(A[2]), "r"(A[3]), "r"(B[0]), "r"(B[1]));
}
#define LDSM4(r0, r1, r2, r3, addr) \
    asm volatile("ldmatrix.sync.aligned.m8n8.x4.shared.b16 {%0,%1,%2,%3}, [%4];" \
                 : "=r"(r0), "=r"(r1), "=r"(r2), "=r"(r3) : "r"(addr))
#define LDSM4T(r0, r1, r2, r3, addr) \
    asm volatile("ldmatrix.sync.aligned.m8n8.x4.trans.shared.b16 {%0,%1,%2,%3}, [%4];" \
                 : "=r"(r0), "=r"(r1), "=r"(r2), "=r"(r3) : "r"(addr))

// -------- no-op (profiler slot positioning) --------
__global__ void k_noop() {}

// -------- kernel 1: flat streaming convert (16B stores) --------
__global__ void __launch_bounds__(256) k_convert(const int* __restrict__ adj) {
    const size_t total8 = (size_t)(NN - 1) * NN / 8;   // uint4-out units (8 ints in)
    size_t gid = (size_t)blockIdx.x * 256 + threadIdx.x;
    size_t stride = (size_t)gridDim.x * 256;
    const int4* src = reinterpret_cast<const int4*>(adj + NN);
    uint4* dst = reinterpret_cast<uint4*>(g_mask);
#pragma unroll
    for (int it = 0; it < 4; it++) {
        size_t t = gid + (size_t)it * stride;
        if (t < total8) {
            int4 v0 = src[2 * t];
            int4 v1 = src[2 * t + 1];
            uint4 o;
            o.x = (v0.x > 0 ? 0x3C00u : 0u) | (v0.y > 0 ? 0x3C000000u : 0u);
            o.y = (v0.z > 0 ? 0x3C00u : 0u) | (v0.w > 0 ? 0x3C000000u : 0u);
            o.z = (v1.x > 0 ? 0x3C00u : 0u) | (v1.y > 0 ? 0x3C000000u : 0u);
            o.w = (v1.z > 0 ? 0x3C00u : 0u) | (v1.w > 0 ? 0x3C000000u : 0u);
            dst[t] = o;
        }
    }
    if (gid < 512)
        reinterpret_cast<uint4*>(g_mask + (size_t)(NN - 1) * NN)[gid] =
            make_uint4(0u, 0u, 0u, 0u);
}

// -------- kernel 2: h = inp@W^T + b (row 0 zeroed); f-split by 2 --------
__global__ void __launch_bounds__(128) k_compute_h(const float* __restrict__ inp,
                                                   const float* __restrict__ W_w,
                                                   const float* __restrict__ W_b,
                                                   const float* __restrict__ a) {
    __shared__ __align__(16) float Wsh[32 * 64];
    __shared__ float bsh[32];
    int tid = threadIdx.x;
    int b = blockIdx.y, nb = blockIdx.x, fs = blockIdx.z;
    int f0 = fs * 32;
    int n = nb * 128 + tid;
    for (int i = tid; i < 32 * 64; i += 128) Wsh[i] = W_w[f0 * 64 + i];
    if (tid < 32) bsh[tid] = W_b[f0 + tid];
    __syncthreads();

    float x[64];
    const float4* src = reinterpret_cast<const float4*>(inp + ((size_t)b * NN + n) * 64);
#pragma unroll
    for (int q = 0; q < 16; q++) {
        float4 v = src[q];
        x[4 * q] = v.x; x[4 * q + 1] = v.y; x[4 * q + 2] = v.z; x[4 * q + 3] = v.w;
    }
    float s1 = 0.f;
#pragma unroll 4
    for (int fl = 0; fl < 32; fl++) {
        const float4* wr = reinterpret_cast<const float4*>(Wsh + fl * 64);
        float t0 = bsh[fl], t1 = 0.f, t2 = 0.f, t3 = 0.f;
#pragma unroll
        for (int q = 0; q < 16; q += 4) {
            float4 w0 = wr[q], w1 = wr[q + 1], w2 = wr[q + 2], w3 = wr[q + 3];
            t0 = fmaf(x[4*q+0],  w0.x, t0); t0 = fmaf(x[4*q+1],  w0.y, t0);
            t0 = fmaf(x[4*q+2],  w0.z, t0); t0 = fmaf(x[4*q+3],  w0.w, t0);
            t1 = fmaf(x[4*q+4],  w1.x, t1); t1 = fmaf(x[4*q+5],  w1.y, t1);
            t1 = fmaf(x[4*q+6],  w1.z, t1); t1 = fmaf(x[4*q+7],  w1.w, t1);
            t2 = fmaf(x[4*q+8],  w2.x, t2); t2 = fmaf(x[4*q+9],  w2.y, t2);
            t2 = fmaf(x[4*q+10], w2.z, t2); t2 = fmaf(x[4*q+11], w2.w, t2);
            t3 = fmaf(x[4*q+12], w3.x, t3); t3 = fmaf(x[4*q+13], w3.y, t3);
            t3 = fmaf(x[4*q+14], w3.z, t3); t3 = fmaf(x[4*q+15], w3.w, t3);
        }
        float acc = (t0 + t1) + (t2 + t3);
        if (n == 0) acc = 0.f;
        int f = f0 + fl;
        g_hT[((size_t)b * 64 + f) * NN + n] = __float2half(acc);
        s1 = fmaf(acc, a[(size_t)f * NN + n], s1);
    }
    g_s1p[fs][b * NN + n] = s1;
}

// -------- kernel 3: hsum[b][f] = sum_n h (from fp16 hT rows) --------
__global__ void __launch_bounds__(256) k_hsum(/* grid (64,8) */) {
    __shared__ float red[256];
    int b = blockIdx.y, f = blockIdx.x, tid = threadIdx.x;
    const __half2* row = reinterpret_cast<const __half2*>(g_hT + ((size_t)b * 64 + f) * NN);
    float s = 0.f;
#pragma unroll
    for (int p = 0; p < 8; p++) {
        float2 v = __half22float2(row[tid + p * 256]);
        s += v.x + v.y;
    }
    red[tid] = s;
    __syncthreads();
    for (int st = 128; st > 0; st >>= 1) {
        if (tid < st) red[tid] += red[tid + st];
        __syncthreads();
    }
    if (tid == 0) g_hsum[b * 64 + f] = red[0];
}

// -------- kernel 4: big GEMM (fp16 mma, A LDSM + B LDSM.trans, 3-stage 1-sync) --------
__device__ __forceinline__ void load_chunk(uint32_t stage, const char* Ah,
                                           const char* Bm, int c, int tid) {
    size_t koffA = (size_t)c * 128;
#pragma unroll
    for (int p = 0; p < 4; p++) {
        int q = tid + p * 256;
        int row = q >> 3, cb = (q & 7) * 16;
        cp16(stage + SW128((uint32_t)(row * 128 + cb)),
             Ah + (size_t)row * 8192 + koffA + cb);
    }
    size_t koffB = (size_t)c * 64 * 8192;
#pragma unroll
    for (int p = 0; p < 4; p++) {
        int q = tid + p * 256;
        int row = q >> 4, cb = (q & 15) * 16;
        uint32_t din = (uint32_t)cb ^ (uint32_t)((row & 15) << 4);
        cp16(stage + 16384u + (uint32_t)(row * 256) + din,
             Bm + koffB + (size_t)row * 8192 + cb);
    }
}

__global__ void __launch_bounds__(256, 2) k_gemm(const float* __restrict__ a) {
    extern __shared__ char smem[];
    uint32_t sb = smem_u32(smem);
    int tid = threadIdx.x, lane = tid & 31, wid = tid >> 5;
    int wm = wid & 3, wn = wid >> 2;
    int mtile = blockIdx.x, i0 = blockIdx.y * 128;
    int kslice = blockIdx.z, c0 = kslice * 32;

    const char* Ah = (const char*)g_hT + (size_t)mtile * 128 * 8192;
    const char* Bm = (const char*)g_mask + (size_t)i0 * 2;

    float acc[2][8][4];
#pragma unroll
    for (int mt = 0; mt < 2; mt++)
#pragma unroll
        for (int nt = 0; nt < 8; nt++)
#pragma unroll
            for (int r = 0; r < 4; r++) acc[mt][nt][r] = 0.f;

    uint32_t cx = (uint32_t)((lane & 7) << 4);
    uint32_t aoff = (uint32_t)(wm * 32 + (lane & 15)) * 128u;
    uint32_t khA = (uint32_t)(((lane >> 4) & 1) << 4);
    uint32_t bj = (uint32_t)(lane & 15);
    uint32_t bcx = bj << 4;
    uint32_t bbase = bj * 256u + (uint32_t)(wn * 64 + ((lane >> 4) << 3)) * 2u;

    load_chunk(sb, Ah, Bm, c0, tid);
    CP_COMMIT();
    load_chunk(sb + STAGE_BYTES, Ah, Bm, c0 + 1, tid);
    CP_COMMIT();

    for (int c = 0; c < 32; c++) {
        asm volatile("cp.async.wait_group 1;" ::: "memory");
        __syncthreads();
        if (c + 2 < 32)
            load_chunk(sb + (uint32_t)((c + 2) % NSTAGE) * STAGE_BYTES, Ah, Bm, c0 + c + 2, tid);
        CP_COMMIT();
        uint32_t so = sb + (uint32_t)(c % NSTAGE) * STAGE_BYTES;
#pragma unroll
        for (int ks = 0; ks < 4; ks++) {
            uint32_t kA = ((uint32_t)(ks * 32) + khA) ^ cx;
            uint32_t bfr[8][2];
#pragma unroll
            for (int ntp = 0; ntp < 4; ntp++) {
                uint32_t boffs = (bbase + (uint32_t)(ntp * 32)) ^ bcx;
                LDSM4T(bfr[2 * ntp][0], bfr[2 * ntp][1], bfr[2 * ntp + 1][0], bfr[2 * ntp + 1][1],
                       so + 16384u + (uint32_t)(ks * 4096) + boffs);
            }
            uint32_t ah[2][4];
#pragma unroll
            for (int mt = 0; mt < 2; mt++)
                LDSM4(ah[mt][0], ah[mt][1], ah[mt][2], ah[mt][3],
                      so + aoff + (uint32_t)mt * 2048 + kA);
#pragma unroll
            for (int mt = 0; mt < 2; mt++)
#pragma unroll
                for (int nt = 0; nt < 8; nt++)
                    mma_f16(acc[mt][nt], ah[mt], bfr[nt]);
        }
    }

    // epilogue: s2p[kslice][b][i] = sum_f C[(b,f)][i] * a2[f][i]
    __syncthreads();
    int tig = lane & 3, grp = lane >> 2;
    float* a2s = (float*)smem;                        // [64][129]
    float* part = (float*)(smem + 64 * 129 * 4);      // [8 warps][64]
    for (int idx = tid; idx < 64 * 128; idx += 256) {
        int f = idx >> 7, cc = idx & 127;
        a2s[f * 129 + cc] = a[(size_t)(64 + f) * NN + i0 + cc];
    }
    __syncthreads();

    float p[8][2];
#pragma unroll
    for (int nt = 0; nt < 8; nt++) { p[nt][0] = 0.f; p[nt][1] = 0.f; }
#pragma unroll
    for (int mt = 0; mt < 2; mt++) {
        int f0 = (wm * 32 + mt * 16 + grp) & 63;
        int f1 = (wm * 32 + mt * 16 + grp + 8) & 63;
#pragma unroll
        for (int nt = 0; nt < 8; nt++) {
            int col = wn * 64 + nt * 8 + tig * 2;
            p[nt][0] += acc[mt][nt][0] * a2s[f0 * 129 + col] +
                        acc[mt][nt][2] * a2s[f1 * 129 + col];
            p[nt][1] += acc[mt][nt][1] * a2s[f0 * 129 + col + 1] +
                        acc[mt][nt][3] * a2s[f1 * 129 + col + 1];
        }
    }
#pragma unroll
    for (int off = 16; off >= 4; off >>= 1)
#pragma unroll
        for (int nt = 0; nt < 8; nt++) {
            p[nt][0] += __shfl_xor_sync(0xFFFFFFFFu, p[nt][0], off);
            p[nt][1] += __shfl_xor_sync(0xFFFFFFFFu, p[nt][1], off);
        }
    if (lane < 4) {
#pragma unroll
        for (int nt = 0; nt < 8; nt++) {
            part[wid * 64 + nt * 8 + tig * 2]     = p[nt][0];
            part[wid * 64 + nt * 8 + tig * 2 + 1] = p[nt][1];
        }
    }
    __syncthreads();
    {
        int bloc = tid >> 7, col = tid & 127;
        int wnn = col >> 6, c64 = col & 63;
        int w0 = wnn * 4 + bloc * 2;
        float v = part[w0 * 64 + c64] + part[(w0 + 1) * 64 + c64];
        g_s2p[kslice][(size_t)(mtile * 2 + bloc) * NN + i0 + col] = v;
    }
}

// -------- kernel 5: out[b,n,f] = leaky(s[b,n] * hsum[b,f]), 2 float4 per thread --------
__global__ void __launch_bounds__(256) k_out(float* __restrict__ out) {
    int b = blockIdx.y, tid = threadIdx.x;
    int n = blockIdx.x * 32 + (tid >> 3);
    int qp = (tid & 7) * 2;
    int off = b * NN + n;
    float s = 0.f;
    if (n != 0) {
        s = g_s1p[0][off] + g_s1p[1][off] + g_s2p[0][off] + g_s2p[1][off];
    }
    const float4* hsp = reinterpret_cast<const float4*>(g_hsum + b * 64);
    float4 ha = hsp[qp], hb = hsp[qp + 1];
    float4 va, vb;
    va.x = s * ha.x; va.y = s * ha.y; va.z = s * ha.z; va.w = s * ha.w;
    vb.x = s * hb.x; vb.y = s * hb.y; vb.z = s * hb.z; vb.w = s * hb.w;
    va.x = va.x >= 0.f ? va.x : NEG_SLOPE * va.x;
    va.y = va.y >= 0.f ? va.y : NEG_SLOPE * va.y;
    va.z = va.z >= 0.f ? va.z : NEG_SLOPE * va.z;
    va.w = va.w >= 0.f ? va.w : NEG_SLOPE * va.w;
    vb.x = vb.x >= 0.f ? vb.x : NEG_SLOPE * vb.x;
    vb.y = vb.y >= 0.f ? vb.y : NEG_SLOPE * vb.y;
    vb.z = vb.z >= 0.f ? vb.z : NEG_SLOPE * vb.z;
    vb.w = vb.w >= 0.f ? vb.w : NEG_SLOPE * vb.w;
    float4* dst = reinterpret_cast<float4*>(out + ((size_t)b * NN + n) * 64);
    dst[qp] = va;
    dst[qp + 1] = vb;
}

extern "C" void kernel_launch(void* const* d_in, const int* in_sizes, int n_in,
                              void* d_out, int out_size) {
    const float* inp = (const float*)d_in[0];
    const int*   adj = (const int*)d_in[1];
    const float* W_w = (const float*)d_in[2];
    const float* W_b = (const float*)d_in[3];
    const float* a   = (const float*)d_in[4];
    float* out = (float*)d_out;
    cudaFuncSetAttribute(k_gemm, cudaFuncAttributeMaxDynamicSharedMemorySize, SMEM_DYN);
    k_noop<<<1, 32>>>();                                        // launch 1
    k_noop<<<1, 32>>>();                                        // launch 2
    k_convert<<<2048, 256>>>(adj);                              // launch 3
    k_compute_h<<<dim3(32, 8, 2), 128>>>(inp, W_w, W_b, a);     // launch 4  <- ncu slot
    k_hsum<<<dim3(64, 8), 256>>>();                             // launch 5
    k_gemm<<<dim3(4, 32, KSPLIT), 256, SMEM_DYN>>>(a);          // launch 6
    k_out<<<dim3(128, 8), 256>>>(out);                          // launch 7
}